// round 6
// baseline (speedup 1.0000x reference)
#include <cuda_runtime.h>

// ----------------------------------------------------------------------------
// SymplecticGyroceptron — R6: packed f32x2 datapath, 4 points/thread.
//
// R5 lesson: L1 (shared crossbar) cost ~ bytes/point. Duplicated weights are
// kept (zero pack MOVs) but amortized over FOUR points per thread:
//   sW1[j] = ((wx,wx),(wy,wy))     ulonglong2  (LDS.128)
//   sW2[j] = ((b,b),(wwx,wwx))     ulonglong2  (LDS.128)
//   sW3[j] = (wwy,wwy)             u64         (LDS.64)
// wwx = -eps*wout*wx, wwy = -eps*wout*wy  (negated: t^2-1 trick).
// 40B per neuron serving 4 points = 10B/pt (same as R4's best).
//
// Per neuron per 4 pts: 3 LDS + 10 FFMA2 + 4 tanh.approx  (~17 issue slots).
// Two independent packed pairs (pts 0/1 and 2/3) double per-thread ILP vs R4.
// ----------------------------------------------------------------------------

#define NEUR 64
#define NLAYERS 16   // 0..7 = psi (eps=1), 8..15 = ni (eps=0.01)

typedef unsigned long long u64;

__device__ ulonglong2 g_w1[NLAYERS * NEUR];
__device__ ulonglong2 g_w2[NLAYERS * NEUR];
__device__ u64        g_w3[NLAYERS * NEUR];
__device__ float2     g_eta[NLAYERS];
__device__ float2     g_cs;

__device__ __forceinline__ u64 pack2(float lo, float hi) {
    u64 d; asm("mov.b64 %0, {%1, %2};" : "=l"(d) : "f"(lo), "f"(hi)); return d;
}
__device__ __forceinline__ void unpack2(u64 d, float& lo, float& hi) {
    asm("mov.b64 {%0, %1}, %2;" : "=f"(lo), "=f"(hi) : "l"(d));
}
__device__ __forceinline__ u64 ffma2(u64 a, u64 b, u64 c) {
    u64 d; asm("fma.rn.f32x2 %0, %1, %2, %3;" : "=l"(d) : "l"(a), "l"(b), "l"(c));
    return d;
}
__device__ __forceinline__ u64 fadd2(u64 a, u64 b) {
    u64 d; asm("add.rn.f32x2 %0, %1, %2;" : "=l"(d) : "l"(a), "l"(b));
    return d;
}
__device__ __forceinline__ u64 fmul2(u64 a, u64 b) {
    u64 d; asm("mul.rn.f32x2 %0, %1, %2;" : "=l"(d) : "l"(a), "l"(b));
    return d;
}
__device__ __forceinline__ u64 tanh2(u64 p) {
    float lo, hi; unpack2(p, lo, hi);
    float tl, th;
    asm("tanh.approx.f32 %0, %1;" : "=f"(tl) : "f"(lo));
    asm("tanh.approx.f32 %0, %1;" : "=f"(th) : "f"(hi));
    return pack2(tl, th);
}

__global__ void prep_kernel(const float* __restrict__ theta0,
                            const float* __restrict__ psi_Win,
                            const float* __restrict__ psi_Wout,
                            const float* __restrict__ psi_b,
                            const float* __restrict__ psi_eta,
                            const float* __restrict__ ni_Win,
                            const float* __restrict__ ni_Wout,
                            const float* __restrict__ ni_b,
                            const float* __restrict__ ni_eta)
{
    int t = threadIdx.x;
    if (t < NLAYERS * NEUR) {
        int l = t >> 6;
        int j = t & 63;
        const float *Win, *Wout, *b;
        float eps;
        int i;
        if (l < 8) { i = l;     Win = psi_Win; Wout = psi_Wout; b = psi_b; eps = 1.0f;  }
        else       { i = l - 8; Win = ni_Win;  Wout = ni_Wout;  b = ni_b;  eps = 0.01f; }
        float w0 = Win[i * 128 + j];        // W_in[i][0][j]
        float w1 = Win[i * 128 + 64 + j];   // W_in[i][1][j]
        float bb = b[i * 64 + j];           // b_in[i][0][j]
        float wo = -Wout[i * 64 + j] * eps; // NEGATED eps*W_out (t^2-1 trick)
        ulonglong2 a; a.x = pack2(w0, w0);       a.y = pack2(w1, w1);
        ulonglong2 c; c.x = pack2(bb, bb);       c.y = pack2(wo*w0, wo*w0);
        g_w1[t] = a;
        g_w2[t] = c;
        g_w3[t] = pack2(wo*w1, wo*w1);
    }
    if (t < NLAYERS) {
        const float* e = (t < 8) ? (psi_eta + t * 2) : (ni_eta + (t - 8) * 2);
        g_eta[t] = make_float2(e[0], e[1]);
    }
    if (t == 0) {
        float th = theta0[0];
        g_cs = make_float2(cosf(th), sinf(th));
    }
}

// grad_V for 4 points: pair a = (pt0,pt1) packed, pair b = (pt2,pt3) packed.
__device__ __forceinline__ void grad4(const ulonglong2* __restrict__ sW1,
                                      const ulonglong2* __restrict__ sW2,
                                      const u64*        __restrict__ sW3,
                                      u64 Y0a, u64 Y1a, u64 Y0b, u64 Y1b,
                                      u64 NEG1,
                                      u64& G0a, u64& G1a, u64& G0b, u64& G1b)
{
    u64 a0 = 0ull, a1 = 0ull, b0 = 0ull, b1 = 0ull;
#pragma unroll 2
    for (int j = 0; j < NEUR; ++j) {
        ulonglong2 w1 = sW1[j];   // (wxx, wyy)
        ulonglong2 w2 = sW2[j];   // (bb, wwxx)
        u64        w3 = sW3[j];   // wwyy
        u64 preA = ffma2(Y0a, w1.x, ffma2(Y1a, w1.y, w2.x));
        u64 preB = ffma2(Y0b, w1.x, ffma2(Y1b, w1.y, w2.x));
        u64 tA = tanh2(preA);
        u64 tB = tanh2(preB);
        u64 mA = ffma2(tA, tA, NEG1);    // t^2 - 1
        u64 mB = ffma2(tB, tB, NEG1);
        a0 = ffma2(mA, w2.y, a0);
        a1 = ffma2(mA, w3,   a1);
        b0 = ffma2(mB, w2.y, b0);
        b1 = ffma2(mB, w3,   b1);
    }
    G0a = a0; G1a = a1; G0b = b0; G1b = b1;
}

__global__ void __launch_bounds__(256, 4)
gyro_kernel(const float4* __restrict__ rin, float4* __restrict__ out,
            int B, int q)
{
    __shared__ ulonglong2 sW1[NLAYERS * NEUR];
    __shared__ ulonglong2 sW2[NLAYERS * NEUR];
    __shared__ u64        sW3[NLAYERS * NEUR];
    __shared__ float2     seta[NLAYERS];
    __shared__ float2     scs;

    for (int i = threadIdx.x; i < NLAYERS * NEUR; i += blockDim.x) {
        sW1[i] = g_w1[i];
        sW2[i] = g_w2[i];
        sW3[i] = g_w3[i];
    }
    if (threadIdx.x < NLAYERS) seta[threadIdx.x] = g_eta[threadIdx.x];
    if (threadIdx.x == 0)      scs = g_cs;
    __syncthreads();

    int idx = blockIdx.x * blockDim.x + threadIdx.x;
    if (idx >= q) return;
    int i1 = idx + q;
    int i2 = idx + 2 * q;
    int i3 = idx + 3 * q;
    bool h1 = i1 < B, h2 = i2 < B, h3 = i3 < B;
    int c1 = h1 ? i1 : idx, c2 = h2 ? i2 : idx, c3 = h3 ? i3 : idx;

    const u64 NEG1 = pack2(-1.0f, -1.0f);

    float4 z0 = rin[idx];
    float4 z1 = rin[c1];
    float4 z2 = rin[c2];
    float4 z3 = rin[c3];
    // pair a = (pt0, pt1), pair b = (pt2, pt3)
    u64 X0a = pack2(z0.x, z1.x), X1a = pack2(z0.y, z1.y);
    u64 Y0a = pack2(z0.z, z1.z), Y1a = pack2(z0.w, z1.w);
    u64 X0b = pack2(z2.x, z3.x), X1b = pack2(z2.y, z3.y);
    u64 Y0b = pack2(z2.z, z3.z), Y1b = pack2(z2.w, z3.w);

    // ---- inverse psi layers, l = 7 .. 0 ----
    for (int l = 7; l >= 0; --l) {
        u64 nE0 = pack2(-seta[l].x, -seta[l].x);
        u64 nE1 = pack2(-seta[l].y, -seta[l].y);
        const ulonglong2* w1 = &sW1[l * NEUR];
        const ulonglong2* w2 = &sW2[l * NEUR];
        const u64*        w3 = &sW3[l * NEUR];
#pragma unroll 1
        for (int k = 0; k < 4; ++k) {
            u64 Yn0a = fadd2(X0a, nE0), Yn1a = fadd2(X1a, nE1);
            u64 Yn0b = fadd2(X0b, nE0), Yn1b = fadd2(X1b, nE1);
            u64 G0a, G1a, G0b, G1b;
            grad4(w1, w2, w3, Yn0a, Yn1a, Yn0b, Yn1b, NEG1, G0a, G1a, G0b, G1b);
            u64 Nx0a = ffma2(Y0a, NEG1, G0a);   // G - Y
            u64 Nx1a = ffma2(Y1a, NEG1, G1a);
            u64 Nx0b = ffma2(Y0b, NEG1, G0b);
            u64 Nx1b = ffma2(Y1b, NEG1, G1b);
            Y0a = Yn0a; Y1a = Yn1a; X0a = Nx0a; X1a = Nx1a;
            Y0b = Yn0b; Y1b = Yn1b; X0b = Nx0b; X1b = Nx1b;
        }
    }

    // ---- circle action (q1 = X0, p1 = Y0) ----
    {
        u64 C  = pack2(scs.x,  scs.x);
        u64 S  = pack2(scs.y,  scs.y);
        u64 nS = pack2(-scs.y, -scs.y);
        u64 qa = X0a, pa = Y0a;
        X0a = ffma2(C, qa, fmul2(S,  pa));
        Y0a = ffma2(C, pa, fmul2(nS, qa));
        u64 qb = X0b, pb = Y0b;
        X0b = ffma2(C, qb, fmul2(S,  pb));
        Y0b = ffma2(C, pb, fmul2(nS, qb));
    }

    // ---- forward layers: l = 0..7 psi, l = 8..15 ni ----
    for (int l = 0; l < NLAYERS; ++l) {
        u64 E0 = pack2(seta[l].x, seta[l].x);
        u64 E1 = pack2(seta[l].y, seta[l].y);
        const ulonglong2* w1 = &sW1[l * NEUR];
        const ulonglong2* w2 = &sW2[l * NEUR];
        const u64*        w3 = &sW3[l * NEUR];
#pragma unroll 1
        for (int k = 0; k < 4; ++k) {
            u64 G0a, G1a, G0b, G1b;
            grad4(w1, w2, w3, Y0a, Y1a, Y0b, Y1b, NEG1, G0a, G1a, G0b, G1b);
            u64 Nx0a = fadd2(Y0a, E0), Nx1a = fadd2(Y1a, E1);
            u64 Ny0a = ffma2(X0a, NEG1, G0a), Ny1a = ffma2(X1a, NEG1, G1a);
            u64 Nx0b = fadd2(Y0b, E0), Nx1b = fadd2(Y1b, E1);
            u64 Ny0b = ffma2(X0b, NEG1, G0b), Ny1b = ffma2(X1b, NEG1, G1b);
            X0a = Nx0a; X1a = Nx1a; Y0a = Ny0a; Y1a = Ny1a;
            X0b = Nx0b; X1b = Nx1b; Y0b = Ny0b; Y1b = Ny1b;
        }
    }

    float p0x0, p1x0, p0x1, p1x1, p0y0, p1y0, p0y1, p1y1;
    unpack2(X0a, p0x0, p1x0); unpack2(X1a, p0x1, p1x1);
    unpack2(Y0a, p0y0, p1y0); unpack2(Y1a, p0y1, p1y1);
    float p2x0, p3x0, p2x1, p3x1, p2y0, p3y0, p2y1, p3y1;
    unpack2(X0b, p2x0, p3x0); unpack2(X1b, p2x1, p3x1);
    unpack2(Y0b, p2y0, p3y0); unpack2(Y1b, p2y1, p3y1);

    out[idx] = make_float4(p0x0, p0x1, p0y0, p0y1);
    if (h1) out[i1] = make_float4(p1x0, p1x1, p1y0, p1y1);
    if (h2) out[i2] = make_float4(p2x0, p2x1, p2y0, p2y1);
    if (h3) out[i3] = make_float4(p3x0, p3x1, p3y0, p3y1);
}

extern "C" void kernel_launch(void* const* d_in, const int* in_sizes, int n_in,
                              void* d_out, int out_size)
{
    const float* r        = (const float*)d_in[0];
    const float* theta0   = (const float*)d_in[1];
    const float* psi_Win  = (const float*)d_in[2];
    const float* psi_Wout = (const float*)d_in[3];
    const float* psi_b    = (const float*)d_in[4];
    const float* psi_eta  = (const float*)d_in[5];
    const float* ni_Win   = (const float*)d_in[6];
    const float* ni_Wout  = (const float*)d_in[7];
    const float* ni_b     = (const float*)d_in[8];
    const float* ni_eta   = (const float*)d_in[9];

    int B = in_sizes[0] / 4;
    int q = (B + 3) / 4;

    prep_kernel<<<1, 1024>>>(theta0, psi_Win, psi_Wout, psi_b, psi_eta,
                             ni_Win, ni_Wout, ni_b, ni_eta);

    int threads = 256;
    int blocks = (q + threads - 1) / threads;
    gyro_kernel<<<blocks, threads>>>((const float4*)r, (float4*)d_out, B, q);
}

// round 7
// speedup vs baseline: 1.1147x; 1.1147x over previous
#include <cuda_runtime.h>

// ----------------------------------------------------------------------------
// SymplecticGyroceptron — R7: packed f32x2, 4 points/thread, occupancy fix.
//
// R6 lesson: 4 pts/thread with 256-thread blocks gave grid=489 < 592 CTA
// slots -> occ 30.9%, latency-bound. Fix: 128-thread blocks (grid 977 ~ one
// full wave at 7 CTAs/SM) + smem shrunk 40->32KB so 7 CTAs fit.
//
// Shared per neuron (32B total, 2x LDS.128, serves 4 points = 8B/pt):
//   sA[j] = ((wx,wx),(wy,wy))    pre-duplicated for packed pre-activation
//   sB[j] = (b, b, wwx, wwy)     (b,b) is a free u64 alias; wwx/wwy packed
//                                 in-loop via 2 MOVs on the idle ALU pipe
// wwx = -eps*wout*wx, wwy = -eps*wout*wy (negated: t^2-1 trick).
//
// Per neuron per 4 pts: 2 LDS + 10 FFMA2 + 4 tanh.approx + 2 MOV.
// ----------------------------------------------------------------------------

#define NEUR 64
#define NLAYERS 16   // 0..7 = psi (eps=1), 8..15 = ni (eps=0.01)
#define TPB 128

typedef unsigned long long u64;

__device__ ulonglong2 g_wA[NLAYERS * NEUR];
__device__ float4     g_wB[NLAYERS * NEUR];
__device__ float2     g_eta[NLAYERS];
__device__ float2     g_cs;

__device__ __forceinline__ u64 pack2(float lo, float hi) {
    u64 d; asm("mov.b64 %0, {%1, %2};" : "=l"(d) : "f"(lo), "f"(hi)); return d;
}
__device__ __forceinline__ void unpack2(u64 d, float& lo, float& hi) {
    asm("mov.b64 {%0, %1}, %2;" : "=f"(lo), "=f"(hi) : "l"(d));
}
__device__ __forceinline__ u64 ffma2(u64 a, u64 b, u64 c) {
    u64 d; asm("fma.rn.f32x2 %0, %1, %2, %3;" : "=l"(d) : "l"(a), "l"(b), "l"(c));
    return d;
}
__device__ __forceinline__ u64 fadd2(u64 a, u64 b) {
    u64 d; asm("add.rn.f32x2 %0, %1, %2;" : "=l"(d) : "l"(a), "l"(b));
    return d;
}
__device__ __forceinline__ u64 fmul2(u64 a, u64 b) {
    u64 d; asm("mul.rn.f32x2 %0, %1, %2;" : "=l"(d) : "l"(a), "l"(b));
    return d;
}
__device__ __forceinline__ u64 tanh2(u64 p) {
    float lo, hi; unpack2(p, lo, hi);
    float tl, th;
    asm("tanh.approx.f32 %0, %1;" : "=f"(tl) : "f"(lo));
    asm("tanh.approx.f32 %0, %1;" : "=f"(th) : "f"(hi));
    return pack2(tl, th);
}

__global__ void prep_kernel(const float* __restrict__ theta0,
                            const float* __restrict__ psi_Win,
                            const float* __restrict__ psi_Wout,
                            const float* __restrict__ psi_b,
                            const float* __restrict__ psi_eta,
                            const float* __restrict__ ni_Win,
                            const float* __restrict__ ni_Wout,
                            const float* __restrict__ ni_b,
                            const float* __restrict__ ni_eta)
{
    int t = threadIdx.x;
    if (t < NLAYERS * NEUR) {
        int l = t >> 6;
        int j = t & 63;
        const float *Win, *Wout, *b;
        float eps;
        int i;
        if (l < 8) { i = l;     Win = psi_Win; Wout = psi_Wout; b = psi_b; eps = 1.0f;  }
        else       { i = l - 8; Win = ni_Win;  Wout = ni_Wout;  b = ni_b;  eps = 0.01f; }
        float w0 = Win[i * 128 + j];        // W_in[i][0][j]
        float w1 = Win[i * 128 + 64 + j];   // W_in[i][1][j]
        float bb = b[i * 64 + j];           // b_in[i][0][j]
        float wo = -Wout[i * 64 + j] * eps; // NEGATED eps*W_out (t^2-1 trick)
        ulonglong2 a; a.x = pack2(w0, w0); a.y = pack2(w1, w1);
        g_wA[t] = a;
        g_wB[t] = make_float4(bb, bb, wo * w0, wo * w1);
    }
    if (t < NLAYERS) {
        const float* e = (t < 8) ? (psi_eta + t * 2) : (ni_eta + (t - 8) * 2);
        g_eta[t] = make_float2(e[0], e[1]);
    }
    if (t == 0) {
        float th = theta0[0];
        g_cs = make_float2(cosf(th), sinf(th));
    }
}

// grad_V for 4 points: pair a = (pt0,pt1) packed, pair b = (pt2,pt3) packed.
__device__ __forceinline__ void grad4(const ulonglong2* __restrict__ sA,
                                      const float4*     __restrict__ sB,
                                      u64 Y0a, u64 Y1a, u64 Y0b, u64 Y1b,
                                      u64 NEG1,
                                      u64& G0a, u64& G1a, u64& G0b, u64& G1b)
{
    u64 a0 = 0ull, a1 = 0ull, b0 = 0ull, b1 = 0ull;
#pragma unroll 2
    for (int j = 0; j < NEUR; ++j) {
        ulonglong2 wa = sA[j];                     // (wxx, wyy)
        float4     wb = sB[j];                     // (b, b, wwx, wwy)
        u64 bb   = pack2(wb.x, wb.y);              // adjacent -> cheap/free
        u64 wwxx = pack2(wb.z, wb.z);              // ALU-pipe MOV
        u64 wwyy = pack2(wb.w, wb.w);              // ALU-pipe MOV
        u64 preA = ffma2(Y0a, wa.x, ffma2(Y1a, wa.y, bb));
        u64 preB = ffma2(Y0b, wa.x, ffma2(Y1b, wa.y, bb));
        u64 tA = tanh2(preA);
        u64 tB = tanh2(preB);
        u64 mA = ffma2(tA, tA, NEG1);              // t^2 - 1
        u64 mB = ffma2(tB, tB, NEG1);
        a0 = ffma2(mA, wwxx, a0);
        a1 = ffma2(mA, wwyy, a1);
        b0 = ffma2(mB, wwxx, b0);
        b1 = ffma2(mB, wwyy, b1);
    }
    G0a = a0; G1a = a1; G0b = b0; G1b = b1;
}

__global__ void __launch_bounds__(TPB, 7)
gyro_kernel(const float4* __restrict__ rin, float4* __restrict__ out,
            int B, int q)
{
    __shared__ ulonglong2 sA[NLAYERS * NEUR];
    __shared__ float4     sB[NLAYERS * NEUR];
    __shared__ float2     seta[NLAYERS];
    __shared__ float2     scs;

    for (int i = threadIdx.x; i < NLAYERS * NEUR; i += TPB) {
        sA[i] = g_wA[i];
        sB[i] = g_wB[i];
    }
    if (threadIdx.x < NLAYERS) seta[threadIdx.x] = g_eta[threadIdx.x];
    if (threadIdx.x == 0)      scs = g_cs;
    __syncthreads();

    int idx = blockIdx.x * TPB + threadIdx.x;
    if (idx >= q) return;
    int i1 = idx + q;
    int i2 = idx + 2 * q;
    int i3 = idx + 3 * q;
    bool h1 = i1 < B, h2 = i2 < B, h3 = i3 < B;
    int c1 = h1 ? i1 : idx, c2 = h2 ? i2 : idx, c3 = h3 ? i3 : idx;

    const u64 NEG1 = pack2(-1.0f, -1.0f);

    float4 z0 = rin[idx];
    float4 z1 = rin[c1];
    float4 z2 = rin[c2];
    float4 z3 = rin[c3];
    u64 X0a = pack2(z0.x, z1.x), X1a = pack2(z0.y, z1.y);
    u64 Y0a = pack2(z0.z, z1.z), Y1a = pack2(z0.w, z1.w);
    u64 X0b = pack2(z2.x, z3.x), X1b = pack2(z2.y, z3.y);
    u64 Y0b = pack2(z2.z, z3.z), Y1b = pack2(z2.w, z3.w);

    // ---- inverse psi layers, l = 7 .. 0 ----
    for (int l = 7; l >= 0; --l) {
        u64 nE0 = pack2(-seta[l].x, -seta[l].x);
        u64 nE1 = pack2(-seta[l].y, -seta[l].y);
        const ulonglong2* wA = &sA[l * NEUR];
        const float4*     wB = &sB[l * NEUR];
#pragma unroll 1
        for (int k = 0; k < 4; ++k) {
            u64 Yn0a = fadd2(X0a, nE0), Yn1a = fadd2(X1a, nE1);
            u64 Yn0b = fadd2(X0b, nE0), Yn1b = fadd2(X1b, nE1);
            u64 G0a, G1a, G0b, G1b;
            grad4(wA, wB, Yn0a, Yn1a, Yn0b, Yn1b, NEG1, G0a, G1a, G0b, G1b);
            u64 Nx0a = ffma2(Y0a, NEG1, G0a);   // G - Y
            u64 Nx1a = ffma2(Y1a, NEG1, G1a);
            u64 Nx0b = ffma2(Y0b, NEG1, G0b);
            u64 Nx1b = ffma2(Y1b, NEG1, G1b);
            Y0a = Yn0a; Y1a = Yn1a; X0a = Nx0a; X1a = Nx1a;
            Y0b = Yn0b; Y1b = Yn1b; X0b = Nx0b; X1b = Nx1b;
        }
    }

    // ---- circle action (q1 = X0, p1 = Y0) ----
    {
        u64 C  = pack2(scs.x,  scs.x);
        u64 S  = pack2(scs.y,  scs.y);
        u64 nS = pack2(-scs.y, -scs.y);
        u64 qa = X0a, pa = Y0a;
        X0a = ffma2(C, qa, fmul2(S,  pa));
        Y0a = ffma2(C, pa, fmul2(nS, qa));
        u64 qb = X0b, pb = Y0b;
        X0b = ffma2(C, qb, fmul2(S,  pb));
        Y0b = ffma2(C, pb, fmul2(nS, qb));
    }

    // ---- forward layers: l = 0..7 psi, l = 8..15 ni ----
    for (int l = 0; l < NLAYERS; ++l) {
        u64 E0 = pack2(seta[l].x, seta[l].x);
        u64 E1 = pack2(seta[l].y, seta[l].y);
        const ulonglong2* wA = &sA[l * NEUR];
        const float4*     wB = &sB[l * NEUR];
#pragma unroll 1
        for (int k = 0; k < 4; ++k) {
            u64 G0a, G1a, G0b, G1b;
            grad4(wA, wB, Y0a, Y1a, Y0b, Y1b, NEG1, G0a, G1a, G0b, G1b);
            u64 Nx0a = fadd2(Y0a, E0), Nx1a = fadd2(Y1a, E1);
            u64 Ny0a = ffma2(X0a, NEG1, G0a), Ny1a = ffma2(X1a, NEG1, G1a);
            u64 Nx0b = fadd2(Y0b, E0), Nx1b = fadd2(Y1b, E1);
            u64 Ny0b = ffma2(X0b, NEG1, G0b), Ny1b = ffma2(X1b, NEG1, G1b);
            X0a = Nx0a; X1a = Nx1a; Y0a = Ny0a; Y1a = Ny1a;
            X0b = Nx0b; X1b = Nx1b; Y0b = Ny0b; Y1b = Ny1b;
        }
    }

    float p0x0, p1x0, p0x1, p1x1, p0y0, p1y0, p0y1, p1y1;
    unpack2(X0a, p0x0, p1x0); unpack2(X1a, p0x1, p1x1);
    unpack2(Y0a, p0y0, p1y0); unpack2(Y1a, p0y1, p1y1);
    float p2x0, p3x0, p2x1, p3x1, p2y0, p3y0, p2y1, p3y1;
    unpack2(X0b, p2x0, p3x0); unpack2(X1b, p2x1, p3x1);
    unpack2(Y0b, p2y0, p3y0); unpack2(Y1b, p2y1, p3y1);

    out[idx] = make_float4(p0x0, p0x1, p0y0, p0y1);
    if (h1) out[i1] = make_float4(p1x0, p1x1, p1y0, p1y1);
    if (h2) out[i2] = make_float4(p2x0, p2x1, p2y0, p2y1);
    if (h3) out[i3] = make_float4(p3x0, p3x1, p3y0, p3y1);
}

extern "C" void kernel_launch(void* const* d_in, const int* in_sizes, int n_in,
                              void* d_out, int out_size)
{
    const float* r        = (const float*)d_in[0];
    const float* theta0   = (const float*)d_in[1];
    const float* psi_Win  = (const float*)d_in[2];
    const float* psi_Wout = (const float*)d_in[3];
    const float* psi_b    = (const float*)d_in[4];
    const float* psi_eta  = (const float*)d_in[5];
    const float* ni_Win   = (const float*)d_in[6];
    const float* ni_Wout  = (const float*)d_in[7];
    const float* ni_b     = (const float*)d_in[8];
    const float* ni_eta   = (const float*)d_in[9];

    int B = in_sizes[0] / 4;
    int q = (B + 3) / 4;

    prep_kernel<<<1, 1024>>>(theta0, psi_Win, psi_Wout, psi_b, psi_eta,
                             ni_Win, ni_Wout, ni_b, ni_eta);

    int blocks = (q + TPB - 1) / TPB;
    gyro_kernel<<<blocks, TPB>>>((const float4*)r, (float4*)d_out, B, q);
}